// round 16
// baseline (speedup 1.0000x reference)
#include <cuda_runtime.h>
#include <cuda_bf16.h>
#include <cstdint>

#define Hh 64
#define Tt 512
#define Bt 4096
#define MB 14            // batches per CTA -> grid 293 (<= 296 slots, balanced wave)
#define NTHREADS 256
#define TX 32

#define ROWB 288         // h row stride bytes (32 j-pairs x 8B + 32 pad)
#define HP   (16 * ROWB) // one h plane (16 rows incl. 2 pad)

typedef unsigned long long ull;

__device__ __forceinline__ void mma_bf16(float* d, const uint32_t* a, const uint32_t* b)
{
    asm("mma.sync.aligned.m16n8k16.row.col.f32.bf16.bf16.f32 "
        "{%0,%1,%2,%3},{%4,%5,%6,%7},{%8,%9},{%0,%1,%2,%3};"
        : "+f"(d[0]), "+f"(d[1]), "+f"(d[2]), "+f"(d[3])
        : "r"(a[0]), "r"(a[1]), "r"(a[2]), "r"(a[3]), "r"(b[0]), "r"(b[1]));
}
// pack {lo16=cvt(v0), hi16=cvt(v1)} in ONE cvt
__device__ __forceinline__ uint32_t bf16x2(float v0, float v1) {
    uint32_t r;
    asm("cvt.rn.bf16x2.f32 %0, %1, %2;" : "=r"(r) : "f"(v1), "f"(v0));
    return r;
}
__device__ __forceinline__ uint32_t pack2(float v0, float v1) {  // setup only
    __nv_bfloat16 l = __float2bfloat16(v0), h = __float2bfloat16(v1);
    return (uint32_t)__bfloat16_as_ushort(l) | ((uint32_t)__bfloat16_as_ushort(h) << 16);
}
__device__ __forceinline__ float bf16of(float v) {   // setup only
    return __bfloat162float(__float2bfloat16(v));
}
__device__ __forceinline__ float tanha(float x) {
    float y;
    asm("tanh.approx.f32 %0, %1;" : "=f"(y) : "f"(x));
    return y;
}

extern "C" __global__ void __launch_bounds__(NTHREADS, 2)
gru_mma_kernel(const float* __restrict__ x,
               const float* __restrict__ W_ih,
               const float* __restrict__ W_hh,
               const float* __restrict__ b_ih,
               const float* __restrict__ b_hh,
               const float* __restrict__ W_out,
               const float* __restrict__ b_out,
               float* __restrict__ out)
{
    __shared__ __align__(16) char hbuf[2 * HP];     // [buf][16 rows][288B]
    __shared__ float xs[16 * 33];
    __shared__ __align__(16) float cj[Hh * 8];      // per-j: 2 x float4
    __shared__ float hfin[16 * 66];

    const int tid  = threadIdx.x;
    const int w    = tid >> 5;            // warp 0..7 -> n-tile (8 j)
    const int lane = tid & 31;
    const int r0   = lane >> 2;
    const int q    = lane & 3;
    const int bBase = blockIdx.x * MB;

    // ---- B fragments in registers (hi/lo): 1 n-tile per gate ----
    uint32_t Bhi[3][4][2], Blo[3][4][2];
    #pragma unroll
    for (int g = 0; g < 3; ++g) {
        const int n = g * Hh + w * 8 + r0;
        #pragma unroll
        for (int kt = 0; kt < 4; ++kt) {
            const float* rp = W_hh + n * Hh + kt * 16 + q * 2;
            float w00 = rp[0], w01 = rp[1], w10 = rp[8], w11 = rp[9];
            float h00 = bf16of(w00), h01 = bf16of(w01);
            float h10 = bf16of(w10), h11 = bf16of(w11);
            Bhi[g][kt][0] = pack2(h00, h01);
            Bhi[g][kt][1] = pack2(h10, h11);
            Blo[g][kt][0] = pack2(w00 - h00, w01 - h01);
            Blo[g][kt][1] = pack2(w10 - h10, w11 - h11);
        }
    }

    if (tid < Hh) {
        int j = tid;
        cj[j * 8 + 0] = W_ih[j];
        cj[j * 8 + 1] = W_ih[Hh + j];
        cj[j * 8 + 2] = W_ih[2 * Hh + j];
        cj[j * 8 + 3] = b_ih[j] + b_hh[j];
        cj[j * 8 + 4] = b_ih[Hh + j] + b_hh[Hh + j];
        cj[j * 8 + 5] = b_ih[2 * Hh + j];
        cj[j * 8 + 6] = b_hh[2 * Hh + j];
        cj[j * 8 + 7] = 0.f;
    }
    for (int i = tid; i < (2 * HP) / 4; i += NTHREADS)
        reinterpret_cast<uint32_t*>(hbuf)[i] = 0;

    float ho[2][2];
    ho[0][0] = ho[0][1] = ho[1][0] = ho[1][1] = 0.f;

    __syncthreads();

    #pragma unroll 2
    for (int t = 0; t < Tt; ++t) {
        if ((t & (TX - 1)) == 0) {
            #pragma unroll
            for (int r = 0; r < 2; ++r) {
                int idx = tid + r * NTHREADS;
                int bi = idx >> 5, tt2 = idx & 31;
                int bg = bBase + bi;
                xs[bi * 33 + tt2] = (bi < MB && bg < Bt) ? x[bg * Tt + t + tt2] : 0.f;
            }
            __syncthreads();
        }

        // ---- A fragments: 16 x LDS.64 ({hi,lo} interleaved per k-pair) ----
        const char* hp = hbuf + (t & 1) * HP;
        uint32_t Ahi[4][4], Alo[4][4];
        #pragma unroll
        for (int kt = 0; kt < 4; ++kt) {
            const int p0 = kt * 8 + q, p1 = p0 + 4;
            ull v0 = *reinterpret_cast<const ull*>(hp + r0 * ROWB + p0 * 8);
            ull v1 = *reinterpret_cast<const ull*>(hp + (r0 + 8) * ROWB + p0 * 8);
            ull v2 = *reinterpret_cast<const ull*>(hp + r0 * ROWB + p1 * 8);
            ull v3 = *reinterpret_cast<const ull*>(hp + (r0 + 8) * ROWB + p1 * 8);
            Ahi[kt][0] = (uint32_t)v0; Alo[kt][0] = (uint32_t)(v0 >> 32);
            Ahi[kt][1] = (uint32_t)v1; Alo[kt][1] = (uint32_t)(v1 >> 32);
            Ahi[kt][2] = (uint32_t)v2; Alo[kt][2] = (uint32_t)(v2 >> 32);
            Ahi[kt][3] = (uint32_t)v3; Alo[kt][3] = (uint32_t)(v3 >> 32);
        }

        // ---- 36 HMMA: hi*hi + lo*hi + hi*lo ----
        float acc[3][4];
        #pragma unroll
        for (int g = 0; g < 3; ++g)
            #pragma unroll
            for (int e = 0; e < 4; ++e) acc[g][e] = 0.f;

        #pragma unroll
        for (int g = 0; g < 3; ++g) {
            #pragma unroll
            for (int kt = 0; kt < 4; ++kt) {
                mma_bf16(acc[g], Ahi[kt], Bhi[g][kt]);
                mma_bf16(acc[g], Alo[kt], Bhi[g][kt]);
                mma_bf16(acc[g], Ahi[kt], Blo[g][kt]);
            }
        }

        // ---- Epilogue: lane owns rows {r0, r0+8}, j in {w*8+2q, +1} ----
        const int tt = t & (TX - 1);
        char* hq = hbuf + ((t + 1) & 1) * HP;
        #pragma unroll
        for (int s = 0; s < 2; ++s) {
            const int row = s * 8 + r0;
            const float xv = xs[row * 33 + tt];
            float hv[2];
            #pragma unroll
            for (int m = 0; m < 2; ++m) {
                const int j = w * 8 + 2 * q + m;
                const float4 c0 = *reinterpret_cast<const float4*>(cj + j * 8);
                const float4 c1 = *reinterpret_cast<const float4*>(cj + j * 8 + 4);
                const int e = s * 2 + m;
                float pr = acc[0][e] + fmaf(xv, c0.x, c0.w);
                float pz = acc[1][e] + fmaf(xv, c0.y, c1.x);
                float r  = fmaf(0.5f, tanha(0.5f * pr), 0.5f);
                float z  = fmaf(0.5f, tanha(0.5f * pz), 0.5f);
                float pn = fmaf(r, acc[2][e] + c1.z, fmaf(xv, c0.z, c1.y));
                float n  = tanha(pn);
                float h  = fmaf(z, ho[s][m] - n, n);
                ho[s][m] = h;
                hv[m] = h;
            }
            // One-cvt hi pack; residuals via shift/mask-as-float; one-cvt lo pack
            uint32_t hiw = bf16x2(hv[0], hv[1]);
            float ah = __uint_as_float(hiw << 16);
            float bh = __uint_as_float(hiw & 0xffff0000u);
            uint32_t low = bf16x2(hv[0] - ah, hv[1] - bh);
            ull v = (ull)hiw | ((ull)low << 32);
            *reinterpret_cast<ull*>(hq + row * ROWB + (w * 4 + q) * 8) = v;
        }
        __syncthreads();
    }

    // ---- Output ----
    #pragma unroll
    for (int s = 0; s < 2; ++s) {
        int bl = s * 8 + r0;
        #pragma unroll
        for (int m = 0; m < 2; ++m) {
            int j = w * 8 + 2 * q + m;
            hfin[bl * 66 + j] = ho[s][m];
        }
    }
    __syncthreads();

    if (tid < MB && bBase + tid < Bt) {
        float sum = b_out[0];
        #pragma unroll
        for (int k = 0; k < Hh; ++k)
            sum = fmaf(hfin[tid * 66 + k], W_out[k], sum);
        out[bBase + tid] = sum;
    }
}

extern "C" void kernel_launch(void* const* d_in, const int* in_sizes, int n_in,
                              void* d_out, int out_size)
{
    const float* x     = (const float*)d_in[0];
    const float* W_ih  = (const float*)d_in[1];
    const float* W_hh  = (const float*)d_in[2];
    const float* b_ih  = (const float*)d_in[3];
    const float* b_hh  = (const float*)d_in[4];
    const float* W_out = (const float*)d_in[5];
    const float* b_out = (const float*)d_in[6];
    float* out = (float*)d_out;

    const int grid = (Bt + MB - 1) / MB;   // 293
    gru_mma_kernel<<<grid, NTHREADS>>>(
        x, W_ih, W_hh, b_ih, b_hh, W_out, b_out, out);
}

// round 17
// speedup vs baseline: 1.3764x; 1.3764x over previous
#include <cuda_runtime.h>
#include <cuda_bf16.h>
#include <cstdint>

#define Hh 64
#define Tt 512
#define Bt 4096
#define MB 16            // batches per CTA -> grid 256, 2 CTAs/SM
#define NTHREADS 256
#define TX 32

#define ROWB 288         // h row stride bytes (32 j-pairs x 8B + 32 pad)
#define HP   (16 * ROWB) // one h plane (4608 B)

typedef unsigned long long ull;

__device__ __forceinline__ void mma_bf16(float* d, const uint32_t* a, const uint32_t* b)
{
    asm("mma.sync.aligned.m16n8k16.row.col.f32.bf16.bf16.f32 "
        "{%0,%1,%2,%3},{%4,%5,%6,%7},{%8,%9},{%0,%1,%2,%3};"
        : "+f"(d[0]), "+f"(d[1]), "+f"(d[2]), "+f"(d[3])
        : "r"(a[0]), "r"(a[1]), "r"(a[2]), "r"(a[3]), "r"(b[0]), "r"(b[1]));
}
// pack {lo16=cvt(v0), hi16=cvt(v1)} in ONE cvt
__device__ __forceinline__ uint32_t bf16x2(float v0, float v1) {
    uint32_t r;
    asm("cvt.rn.bf16x2.f32 %0, %1, %2;" : "=r"(r) : "f"(v1), "f"(v0));
    return r;
}
__device__ __forceinline__ uint32_t pack2(float v0, float v1) {  // setup only
    __nv_bfloat16 l = __float2bfloat16(v0), h = __float2bfloat16(v1);
    return (uint32_t)__bfloat16_as_ushort(l) | ((uint32_t)__bfloat16_as_ushort(h) << 16);
}
__device__ __forceinline__ float bf16of(float v) {   // setup only
    return __bfloat162float(__float2bfloat16(v));
}
__device__ __forceinline__ float tanha(float x) {
    float y;
    asm("tanh.approx.f32 %0, %1;" : "=f"(y) : "f"(x));
    return y;
}

extern "C" __global__ void __launch_bounds__(NTHREADS, 2)
gru_mma_kernel(const float* __restrict__ x,
               const float* __restrict__ W_ih,
               const float* __restrict__ W_hh,
               const float* __restrict__ b_ih,
               const float* __restrict__ b_hh,
               const float* __restrict__ W_out,
               const float* __restrict__ b_out,
               float* __restrict__ out)
{
    __shared__ __align__(16) char hbuf[2 * HP];     // [buf][16 rows][288B]
    __shared__ float xs[MB * 33];
    __shared__ __align__(16) float cj[Hh * 8];      // per-j: 2 x float4
    __shared__ float hfin[MB * 66];

    const int tid  = threadIdx.x;
    const int w    = tid >> 5;            // warp 0..7 -> n-tile (8 j)
    const int lane = tid & 31;
    const int r0   = lane >> 2;
    const int q    = lane & 3;
    const int bBase = blockIdx.x * MB;

    // ---- B fragments in registers (hi/lo): 1 n-tile per gate ----
    uint32_t Bhi[3][4][2], Blo[3][4][2];
    #pragma unroll
    for (int g = 0; g < 3; ++g) {
        const int n = g * Hh + w * 8 + r0;
        #pragma unroll
        for (int kt = 0; kt < 4; ++kt) {
            const float* rp = W_hh + n * Hh + kt * 16 + q * 2;
            float w00 = rp[0], w01 = rp[1], w10 = rp[8], w11 = rp[9];
            float h00 = bf16of(w00), h01 = bf16of(w01);
            float h10 = bf16of(w10), h11 = bf16of(w11);
            Bhi[g][kt][0] = pack2(h00, h01);
            Bhi[g][kt][1] = pack2(h10, h11);
            Blo[g][kt][0] = pack2(w00 - h00, w01 - h01);
            Blo[g][kt][1] = pack2(w10 - h10, w11 - h11);
        }
    }

    // Per-j epilogue constants -> shared LUT
    if (tid < Hh) {
        int j = tid;
        cj[j * 8 + 0] = W_ih[j];
        cj[j * 8 + 1] = W_ih[Hh + j];
        cj[j * 8 + 2] = W_ih[2 * Hh + j];
        cj[j * 8 + 3] = b_ih[j] + b_hh[j];
        cj[j * 8 + 4] = b_ih[Hh + j] + b_hh[Hh + j];
        cj[j * 8 + 5] = b_ih[2 * Hh + j];
        cj[j * 8 + 6] = b_hh[2 * Hh + j];
        cj[j * 8 + 7] = 0.f;
    }
    for (int i = tid; i < (2 * HP) / 4; i += NTHREADS)
        reinterpret_cast<uint32_t*>(hbuf)[i] = 0;

    float ho[2][2];                        // [row s][m]
    ho[0][0] = ho[0][1] = ho[1][0] = ho[1][1] = 0.f;

    __syncthreads();

    for (int t = 0; t < Tt; ++t) {
        if ((t & (TX - 1)) == 0) {
            #pragma unroll
            for (int r = 0; r < (MB * TX) / NTHREADS; ++r) {
                int idx = tid + r * NTHREADS;
                int bi = idx >> 5, tt2 = idx & 31;
                xs[bi * 33 + tt2] = x[(bBase + bi) * Tt + t + tt2];
            }
            __syncthreads();
        }

        // ---- A fragments: 16 x LDS.64 ({hi,lo} interleaved per k-pair) ----
        const char* hp = hbuf + (t & 1) * HP;
        uint32_t Ahi[4][4], Alo[4][4];
        #pragma unroll
        for (int kt = 0; kt < 4; ++kt) {
            const int p0 = kt * 8 + q, p1 = p0 + 4;
            ull v0 = *reinterpret_cast<const ull*>(hp + r0 * ROWB + p0 * 8);
            ull v1 = *reinterpret_cast<const ull*>(hp + (r0 + 8) * ROWB + p0 * 8);
            ull v2 = *reinterpret_cast<const ull*>(hp + r0 * ROWB + p1 * 8);
            ull v3 = *reinterpret_cast<const ull*>(hp + (r0 + 8) * ROWB + p1 * 8);
            Ahi[kt][0] = (uint32_t)v0; Alo[kt][0] = (uint32_t)(v0 >> 32);
            Ahi[kt][1] = (uint32_t)v1; Alo[kt][1] = (uint32_t)(v1 >> 32);
            Ahi[kt][2] = (uint32_t)v2; Alo[kt][2] = (uint32_t)(v2 >> 32);
            Ahi[kt][3] = (uint32_t)v3; Alo[kt][3] = (uint32_t)(v3 >> 32);
        }

        // ---- 36 HMMA, product-pass outer / gate inner: same-acc deps spaced by 3 ----
        float acc[3][4];
        #pragma unroll
        for (int g = 0; g < 3; ++g)
            #pragma unroll
            for (int e = 0; e < 4; ++e) acc[g][e] = 0.f;

        #pragma unroll
        for (int kt = 0; kt < 4; ++kt) {
            #pragma unroll
            for (int g = 0; g < 3; ++g)
                mma_bf16(acc[g], Ahi[kt], Bhi[g][kt]);
        }
        #pragma unroll
        for (int kt = 0; kt < 4; ++kt) {
            #pragma unroll
            for (int g = 0; g < 3; ++g)
                mma_bf16(acc[g], Alo[kt], Bhi[g][kt]);
        }
        #pragma unroll
        for (int kt = 0; kt < 4; ++kt) {
            #pragma unroll
            for (int g = 0; g < 3; ++g)
                mma_bf16(acc[g], Ahi[kt], Blo[g][kt]);
        }

        // ---- Epilogue: lane owns rows {r0, r0+8}, j in {w*8+2q, +1} ----
        const int tt = t & (TX - 1);
        char* hq = hbuf + ((t + 1) & 1) * HP;
        #pragma unroll
        for (int s = 0; s < 2; ++s) {
            const int row = s * 8 + r0;
            const float xv = xs[row * 33 + tt];
            float hv[2];
            #pragma unroll
            for (int m = 0; m < 2; ++m) {
                const int j = w * 8 + 2 * q + m;
                const float4 c0 = *reinterpret_cast<const float4*>(cj + j * 8);
                const float4 c1 = *reinterpret_cast<const float4*>(cj + j * 8 + 4);
                const int e = s * 2 + m;
                float pr = acc[0][e] + fmaf(xv, c0.x, c0.w);
                float pz = acc[1][e] + fmaf(xv, c0.y, c1.x);
                float r  = fmaf(0.5f, tanha(0.5f * pr), 0.5f);
                float z  = fmaf(0.5f, tanha(0.5f * pz), 0.5f);
                float pn = fmaf(r, acc[2][e] + c1.z, fmaf(xv, c0.z, c1.y));
                float n  = tanha(pn);
                float h  = fmaf(z, ho[s][m] - n, n);
                ho[s][m] = h;
                hv[m] = h;
            }
            // One-cvt hi pack; residuals via shift/mask-as-float; one-cvt lo pack
            uint32_t hiw = bf16x2(hv[0], hv[1]);
            float ah = __uint_as_float(hiw << 16);
            float bh = __uint_as_float(hiw & 0xffff0000u);
            uint32_t low = bf16x2(hv[0] - ah, hv[1] - bh);
            ull v = (ull)hiw | ((ull)low << 32);
            *reinterpret_cast<ull*>(hq + row * ROWB + (w * 4 + q) * 8) = v;
        }
        __syncthreads();
    }

    // ---- Output ----
    #pragma unroll
    for (int s = 0; s < 2; ++s) {
        int bl = s * 8 + r0;
        #pragma unroll
        for (int m = 0; m < 2; ++m) {
            int j = w * 8 + 2 * q + m;
            hfin[bl * 66 + j] = ho[s][m];
        }
    }
    __syncthreads();

    if (tid < MB) {
        float sum = b_out[0];
        #pragma unroll
        for (int k = 0; k < Hh; ++k)
            sum = fmaf(hfin[tid * 66 + k], W_out[k], sum);
        out[bBase + tid] = sum;
    }
}

extern "C" void kernel_launch(void* const* d_in, const int* in_sizes, int n_in,
                              void* d_out, int out_size)
{
    const float* x     = (const float*)d_in[0];
    const float* W_ih  = (const float*)d_in[1];
    const float* W_hh  = (const float*)d_in[2];
    const float* b_ih  = (const float*)d_in[3];
    const float* b_hh  = (const float*)d_in[4];
    const float* W_out = (const float*)d_in[5];
    const float* b_out = (const float*)d_in[6];
    float* out = (float*)d_out;

    gru_mma_kernel<<<Bt / MB, NTHREADS>>>(
        x, W_ih, W_hh, b_ih, b_hh, W_out, b_out, out);
}